// round 4
// baseline (speedup 1.0000x reference)
#include <cuda_runtime.h>
#include <cuda_bf16.h>
#include <cstdint>

// ---------------- problem constants ----------------
#define NPAIRS 4096
#define TWO_N  8192
#define DIM    256
#define COS_EPS 1e-8f

// ---------------- scratch (device globals, no allocation) ----------------
__device__ __align__(256) __nv_bfloat16 g_nhat[TWO_N * DIM]; // normalized reps, bf16
__device__ float g_rowsum[TWO_N];
__device__ float g_pos[NPAIRS];
__device__ float g_partials[64];

// ---------------- PTX helpers (sm_103 base target: ldmatrix + mma.sync only) ----------------
__device__ __forceinline__ uint32_t smem_u32(const void* p) {
    uint32_t a;
    asm("{ .reg .u64 t; cvta.to.shared.u64 t, %1; cvt.u32.u64 %0, t; }" : "=r"(a) : "l"(p));
    return a;
}

__device__ __forceinline__ void ldsm_x4(uint32_t addr, uint32_t* r) {
    asm volatile("ldmatrix.sync.aligned.m8n8.x4.shared.b16 {%0,%1,%2,%3}, [%4];"
        : "=r"(r[0]), "=r"(r[1]), "=r"(r[2]), "=r"(r[3]) : "r"(addr));
}

__device__ __forceinline__ void mma16816(float* d, const uint32_t* a, const uint32_t* b) {
    asm volatile("mma.sync.aligned.m16n8k16.row.col.f32.bf16.bf16.f32 "
        "{%0,%1,%2,%3}, {%4,%5,%6,%7}, {%8,%9}, {%0,%1,%2,%3};"
        : "+f"(d[0]), "+f"(d[1]), "+f"(d[2]), "+f"(d[3])
        : "r"(a[0]), "r"(a[1]), "r"(a[2]), "r"(a[3]), "r"(b[0]), "r"(b[1]));
}

// ---------------- kernel 1: normalize + positives + rowsum zeroing ----------------
__device__ __forceinline__ uint32_t pack_bf2(float a, float b) {
    __nv_bfloat162 t = __floats2bfloat162_rn(a, b);
    return *reinterpret_cast<uint32_t*>(&t);
}

__global__ void k_norm(const float* __restrict__ zis, const float* __restrict__ zjs) {
    int tid = threadIdx.x;
    int gid = blockIdx.x * 256 + tid;
    if (gid < TWO_N) g_rowsum[gid] = 0.0f;

    int w = blockIdx.x * 8 + (tid >> 5);   // pair index 0..4095
    int lane = tid & 31;

    const float4* zi = (const float4*)zis + (size_t)w * 64;
    const float4* zj = (const float4*)zjs + (size_t)w * 64;
    float4 a0 = zi[lane], a1 = zi[lane + 32];
    float4 b0 = zj[lane], b1 = zj[lane + 32];

    float si = a0.x*a0.x + a0.y*a0.y + a0.z*a0.z + a0.w*a0.w
             + a1.x*a1.x + a1.y*a1.y + a1.z*a1.z + a1.w*a1.w;
    float sj = b0.x*b0.x + b0.y*b0.y + b0.z*b0.z + b0.w*b0.w
             + b1.x*b1.x + b1.y*b1.y + b1.z*b1.z + b1.w*b1.w;
    float dv = a0.x*b0.x + a0.y*b0.y + a0.z*b0.z + a0.w*b0.w
             + a1.x*b1.x + a1.y*b1.y + a1.z*b1.z + a1.w*b1.w;
    #pragma unroll
    for (int o = 16; o; o >>= 1) {
        si += __shfl_xor_sync(0xFFFFFFFFu, si, o);
        sj += __shfl_xor_sync(0xFFFFFFFFu, sj, o);
        dv += __shfl_xor_sync(0xFFFFFFFFu, dv, o);
    }
    float ni = sqrtf(si), nj = sqrtf(sj);
    if (lane == 0) g_pos[w] = dv / fmaxf(ni * nj, COS_EPS);

    float ii = 1.0f / ni, ji = 1.0f / nj;
    // reps = [zjs ; zis]: row w <- zjs[w]/nj, row w+NPAIRS <- zis[w]/ni
    uint2* rj = (uint2*)g_nhat + (size_t)w * 64;
    uint2* ri = (uint2*)g_nhat + (size_t)(w + NPAIRS) * 64;
    uint2 vj0 = { pack_bf2(b0.x*ji, b0.y*ji), pack_bf2(b0.z*ji, b0.w*ji) };
    uint2 vj1 = { pack_bf2(b1.x*ji, b1.y*ji), pack_bf2(b1.z*ji, b1.w*ji) };
    uint2 vi0 = { pack_bf2(a0.x*ii, a0.y*ii), pack_bf2(a0.z*ii, a0.w*ii) };
    uint2 vi1 = { pack_bf2(a1.x*ii, a1.y*ii), pack_bf2(a1.z*ii, a1.w*ii) };
    rj[lane] = vj0;  rj[lane + 32] = vj1;
    ri[lane] = vi0;  ri[lane + 32] = vi1;
}

// ---------------- kernel 2: symmetric mma.sync GEMM tile + exp + row/col partial sums ----
// Tiles (tm, tn) with tm <= tn only. SMEM: A tile 128x256 bf16 (64KB) + B tile (64KB).
// Layout: [row][k] bf16, 512B row pitch, 16B-unit swizzle: off ^= (row&7)<<4.
static constexpr uint32_t TILEB = 128u * 512u;      // 64 KB per tile
static constexpr uint32_t SMEM_TOTAL = 2u * TILEB;  // 128 KB

__global__ __launch_bounds__(256, 1) void k_gemm() {
    extern __shared__ uint8_t smem[];
    int tm = blockIdx.y, tn = blockIdx.x;
    if (tm > tn) return;                     // symmetry: upper-triangular tiles only
    int tid = threadIdx.x, wid = tid >> 5, lane = tid & 31;
    int wm = wid >> 2, wn = wid & 3;         // warp grid 2(m) x 4(n); warp tile 64x32
    int g = lane >> 2, q = lane & 3;
    bool diag = (tm == tn);

    // ---- global -> shared (swizzled); diag tiles share one copy ----
    const uint4* __restrict__ src = (const uint4*)g_nhat; // 32 x 16B per row
    #pragma unroll
    for (int it = 0; it < 16; ++it) {
        int idx = it * 256 + tid;
        int r = idx >> 5, kv = idx & 31;
        uint32_t off = (uint32_t)(r * 512 + kv * 16);
        uint32_t sw = off ^ ((uint32_t)(r & 7) << 4);
        *(uint4*)(smem + sw) = src[(size_t)(tm * 128 + r) * 32 + kv];
        if (!diag)
            *(uint4*)(smem + TILEB + sw) = src[(size_t)(tn * 128 + r) * 32 + kv];
    }
    __syncthreads();

    uint32_t sA = smem_u32(smem);
    uint32_t sB = diag ? sA : (sA + TILEB);

    float acc[4][4][4];
    #pragma unroll
    for (int i = 0; i < 4; ++i)
        #pragma unroll
        for (int j = 0; j < 4; ++j)
            #pragma unroll
            for (int x = 0; x < 4; ++x) acc[i][j][x] = 0.f;

    int l7 = lane & 7;
    // ldmatrix lane-address generators (see fragment layout derivation)
    int ra_base = wm * 64 + l7 + ((lane >> 3) & 1) * 8;  // A rows
    int ka_base = (lane >> 4) * 16;                      // A k-bytes sub-offset
    int rb_base = wn * 32 + l7 + (lane >> 4) * 8;        // B n-rows
    int kb_base = ((lane >> 3) & 1) * 16;                // B k-bytes sub-offset

    #pragma unroll 2
    for (int kk = 0; kk < 16; ++kk) {
        uint32_t af[4][4];
        #pragma unroll
        for (int i = 0; i < 4; ++i) {
            int r = ra_base + i * 16;
            uint32_t off = (uint32_t)(r * 512 + kk * 32 + ka_base);
            ldsm_x4(sA + (off ^ ((uint32_t)(r & 7) << 4)), af[i]);
        }
        uint32_t bf[2][4];
        #pragma unroll
        for (int j2 = 0; j2 < 2; ++j2) {
            int r = rb_base + j2 * 16;
            uint32_t off = (uint32_t)(r * 512 + kk * 32 + kb_base);
            ldsm_x4(sB + (off ^ ((uint32_t)(r & 7) << 4)), bf[j2]);
        }
        #pragma unroll
        for (int i = 0; i < 4; ++i)
            #pragma unroll
            for (int j = 0; j < 4; ++j)
                mma16816(acc[i][j], af[i], &bf[j >> 1][(j & 1) * 2]);
    }
    __syncthreads();   // smem tiles no longer needed; reuse for reductions

    float* rAcc = (float*)smem;        // 128 row partials (tm rows)
    float* cAcc = rAcc + 128;          // 128 col partials (tn rows, via symmetry)
    ((float*)smem)[tid] = 0.f;         // 256 threads zero 256 floats
    __syncthreads();

    float rs[4][2], cs[4][2];
    #pragma unroll
    for (int i = 0; i < 4; ++i) { rs[i][0] = 0.f; rs[i][1] = 0.f; }
    #pragma unroll
    for (int j = 0; j < 4; ++j) { cs[j][0] = 0.f; cs[j][1] = 0.f; }

    #pragma unroll
    for (int i = 0; i < 4; ++i) {
        int R0 = wm * 64 + i * 16 + g, R1 = R0 + 8;
        #pragma unroll
        for (int j = 0; j < 4; ++j) {
            int C0 = wn * 32 + j * 8 + 2 * q, C1 = C0 + 1;
            float e00 = __expf(2.0f * acc[i][j][0]);  // logits = sim / 0.5
            float e01 = __expf(2.0f * acc[i][j][1]);
            float e10 = __expf(2.0f * acc[i][j][2]);
            float e11 = __expf(2.0f * acc[i][j][3]);
            if (diag) {                               // mask self-diagonal
                if (R0 == C0) e00 = 0.f;
                if (R0 == C1) e01 = 0.f;
                if (R1 == C0) e10 = 0.f;
                if (R1 == C1) e11 = 0.f;
            }
            rs[i][0] += e00 + e01;  rs[i][1] += e10 + e11;
            cs[j][0] += e00 + e10;  cs[j][1] += e01 + e11;
        }
    }
    // row partials: lanes sharing g share rows -> reduce over q
    #pragma unroll
    for (int i = 0; i < 4; ++i)
        #pragma unroll
        for (int h = 0; h < 2; ++h) {
            float v = rs[i][h];
            v += __shfl_xor_sync(0xFFFFFFFFu, v, 1);
            v += __shfl_xor_sync(0xFFFFFFFFu, v, 2);
            if (q == 0) atomicAdd(&rAcc[wm * 64 + i * 16 + g + h * 8], v);
        }
    // col partials: lanes sharing q share cols -> reduce over g (only off-diagonal tiles)
    if (!diag) {
        #pragma unroll
        for (int j = 0; j < 4; ++j)
            #pragma unroll
            for (int h = 0; h < 2; ++h) {
                float v = cs[j][h];
                v += __shfl_xor_sync(0xFFFFFFFFu, v, 4);
                v += __shfl_xor_sync(0xFFFFFFFFu, v, 8);
                v += __shfl_xor_sync(0xFFFFFFFFu, v, 16);
                if (g == 0) atomicAdd(&cAcc[wn * 32 + j * 8 + 2 * q + h], v);
            }
    }
    __syncthreads();
    if (tid < 128) {
        atomicAdd(&g_rowsum[tm * 128 + tid], rAcc[tid]);
        if (!diag) atomicAdd(&g_rowsum[tn * 128 + tid], cAcc[tid]);
    }
}

// ---------------- kernel 3: per-row log + positive subtraction -> 64 partials ----------------
__global__ void k_rowred() {
    __shared__ float sh[4];
    int r = blockIdx.x * 128 + threadIdx.x;  // 64 * 128 = 8192 rows
    float v = logf(g_rowsum[r]) - 2.0f * g_pos[r & (NPAIRS - 1)];
    #pragma unroll
    for (int o = 16; o; o >>= 1) v += __shfl_xor_sync(0xFFFFFFFFu, v, o);
    if ((threadIdx.x & 31) == 0) sh[threadIdx.x >> 5] = v;
    __syncthreads();
    if (threadIdx.x == 0) g_partials[blockIdx.x] = sh[0] + sh[1] + sh[2] + sh[3];
}

// ---------------- kernel 4: final reduce ----------------
__global__ void k_final(float* __restrict__ out) {
    int l = threadIdx.x;
    float v = g_partials[l] + g_partials[l + 32];
    #pragma unroll
    for (int o = 16; o; o >>= 1) v += __shfl_xor_sync(0xFFFFFFFFu, v, o);
    if (l == 0) out[0] = v / (float)TWO_N;
}

// ---------------- launch ----------------
extern "C" void kernel_launch(void* const* d_in, const int* in_sizes, int n_in,
                              void* d_out, int out_size) {
    const float* zis = (const float*)d_in[0];
    const float* zjs = (const float*)d_in[1];
    float* out = (float*)d_out;

    cudaFuncSetAttribute(k_gemm, cudaFuncAttributeMaxDynamicSharedMemorySize, SMEM_TOTAL);

    k_norm<<<512, 256>>>(zis, zjs);
    dim3 grid(64, 64);                 // (tn, tm); tm > tn blocks exit immediately
    k_gemm<<<grid, 256, SMEM_TOTAL>>>();
    k_rowred<<<64, 128>>>();
    k_final<<<1, 32>>>(out);
}

// round 5
// speedup vs baseline: 1.3617x; 1.3617x over previous
#include <cuda_runtime.h>
#include <cuda_bf16.h>
#include <cstdint>

// ---------------- problem constants ----------------
#define NPAIRS 4096
#define TWO_N  8192
#define DIM    256
#define NT     64          // 8192/128 tiles per side
#define NTRI   2080        // NT*(NT+1)/2 upper-triangular tiles
#define COS_EPS 1e-8f

// ---------------- scratch (device globals, no allocation) ----------------
__device__ __align__(256) uint32_t g_nhat[TWO_N * DIM / 4]; // normalized reps, e4m3 (2MB)
__device__ float g_rowsum[TWO_N];
__device__ float g_pos[NPAIRS];
__device__ float g_partials[64];

// ---------------- PTX helpers (sm_103 base target: ldmatrix + legacy mma only) -------
__device__ __forceinline__ uint32_t smem_u32(const void* p) {
    uint32_t a;
    asm("{ .reg .u64 t; cvta.to.shared.u64 t, %1; cvt.u32.u64 %0, t; }" : "=r"(a) : "l"(p));
    return a;
}

__device__ __forceinline__ void ldsm_x4(uint32_t addr, uint32_t* r) {
    asm volatile("ldmatrix.sync.aligned.m8n8.x4.shared.b16 {%0,%1,%2,%3}, [%4];"
        : "=r"(r[0]), "=r"(r[1]), "=r"(r[2]), "=r"(r[3]) : "r"(addr));
}

// fp8 e4m3 MMA: byte-layout of fragments matches b16 ldmatrix loads exactly.
__device__ __forceinline__ void mma16832_e4m3(float* d, const uint32_t* a, const uint32_t* b) {
    asm volatile("mma.sync.aligned.m16n8k32.row.col.f32.e4m3.e4m3.f32 "
        "{%0,%1,%2,%3}, {%4,%5,%6,%7}, {%8,%9}, {%0,%1,%2,%3};"
        : "+f"(d[0]), "+f"(d[1]), "+f"(d[2]), "+f"(d[3])
        : "r"(a[0]), "r"(a[1]), "r"(a[2]), "r"(a[3]), "r"(b[0]), "r"(b[1]));
}

__device__ __forceinline__ uint32_t pack_e4m3x4(float x0, float x1, float x2, float x3) {
    uint16_t lo, hi;
    asm("cvt.rn.satfinite.e4m3x2.f32 %0, %1, %2;" : "=h"(lo) : "f"(x1), "f"(x0));
    asm("cvt.rn.satfinite.e4m3x2.f32 %0, %1, %2;" : "=h"(hi) : "f"(x3), "f"(x2));
    return (uint32_t)lo | ((uint32_t)hi << 16);
}

// ---------------- kernel 1: normalize + positives (fp32, exact) + rowsum zero --------
__global__ void k_norm(const float* __restrict__ zis, const float* __restrict__ zjs) {
    int tid = threadIdx.x;
    int gid = blockIdx.x * 256 + tid;
    if (gid < TWO_N) g_rowsum[gid] = 0.0f;

    int w = blockIdx.x * 8 + (tid >> 5);   // pair index 0..4095
    int lane = tid & 31;

    const float4* zi = (const float4*)zis + (size_t)w * 64;
    const float4* zj = (const float4*)zjs + (size_t)w * 64;
    float4 a0 = zi[lane], a1 = zi[lane + 32];
    float4 b0 = zj[lane], b1 = zj[lane + 32];

    float si = a0.x*a0.x + a0.y*a0.y + a0.z*a0.z + a0.w*a0.w
             + a1.x*a1.x + a1.y*a1.y + a1.z*a1.z + a1.w*a1.w;
    float sj = b0.x*b0.x + b0.y*b0.y + b0.z*b0.z + b0.w*b0.w
             + b1.x*b1.x + b1.y*b1.y + b1.z*b1.z + b1.w*b1.w;
    float dv = a0.x*b0.x + a0.y*b0.y + a0.z*b0.z + a0.w*b0.w
             + a1.x*b1.x + a1.y*b1.y + a1.z*b1.z + a1.w*b1.w;
    #pragma unroll
    for (int o = 16; o; o >>= 1) {
        si += __shfl_xor_sync(0xFFFFFFFFu, si, o);
        sj += __shfl_xor_sync(0xFFFFFFFFu, sj, o);
        dv += __shfl_xor_sync(0xFFFFFFFFu, dv, o);
    }
    float ni = sqrtf(si), nj = sqrtf(sj);
    if (lane == 0) g_pos[w] = dv / fmaxf(ni * nj, COS_EPS);

    float ii = 1.0f / ni, ji = 1.0f / nj;
    // reps = [zjs ; zis]: row w <- zjs[w]/nj, row w+NPAIRS <- zis[w]/ni  (e4m3)
    uint32_t* rj = g_nhat + (size_t)w * 64;
    uint32_t* ri = g_nhat + (size_t)(w + NPAIRS) * 64;
    rj[lane]      = pack_e4m3x4(b0.x*ji, b0.y*ji, b0.z*ji, b0.w*ji);
    rj[lane + 32] = pack_e4m3x4(b1.x*ji, b1.y*ji, b1.z*ji, b1.w*ji);
    ri[lane]      = pack_e4m3x4(a0.x*ii, a0.y*ii, a0.z*ii, a0.w*ii);
    ri[lane + 32] = pack_e4m3x4(a1.x*ii, a1.y*ii, a1.z*ii, a1.w*ii);
}

// ---------------- kernel 2: symmetric fp8 mma GEMM tile + exp + row/col partial sums -
// Triangular tiles tm <= tn only. SMEM: two 128x256B e4m3 tiles (32KB each).
// Layout: [row][k] fp8, 256B row pitch, 16B-unit swizzle: off ^= (row&7)<<4.
static constexpr uint32_t TILEB = 128u * 256u;      // 32 KB per tile
static constexpr uint32_t SMEM_TOTAL = 2u * TILEB;  // 64 KB -> occupancy 2

__global__ __launch_bounds__(256, 2) void k_gemm() {
    extern __shared__ uint8_t smem[];
    // triangular decode: linear t -> (tm, tn), tm <= tn
    int t = blockIdx.x;
    int tm = (int)(64.5f - sqrtf(64.5f * 64.5f - 2.0f * (float)t));
    while (NT * tm - tm * (tm - 1) / 2 > t) --tm;
    while (NT * (tm + 1) - (tm + 1) * tm / 2 <= t) ++tm;
    int tn = tm + (t - (NT * tm - tm * (tm - 1) / 2));

    int tid = threadIdx.x, wid = tid >> 5, lane = tid & 31;
    int wm = wid >> 2, wn = wid & 3;         // warp grid 2(m) x 4(n); warp tile 64x32
    int g = lane >> 2, q = lane & 3;
    bool diag = (tm == tn);

    // ---- global -> shared (swizzled); diag tiles share one copy ----
    const uint4* __restrict__ src = (const uint4*)g_nhat; // 16 x 16B per row
    #pragma unroll
    for (int it = 0; it < 8; ++it) {
        int idx = it * 256 + tid;
        int r = idx >> 4, kv = idx & 15;
        uint32_t off = (uint32_t)(r * 256 + kv * 16);
        uint32_t sw = off ^ ((uint32_t)(r & 7) << 4);
        *(uint4*)(smem + sw) = src[(size_t)(tm * 128 + r) * 16 + kv];
        if (!diag)
            *(uint4*)(smem + TILEB + sw) = src[(size_t)(tn * 128 + r) * 16 + kv];
    }
    __syncthreads();

    uint32_t sA = smem_u32(smem);
    uint32_t sB = diag ? sA : (sA + TILEB);

    float acc[4][4][4];
    #pragma unroll
    for (int i = 0; i < 4; ++i)
        #pragma unroll
        for (int j = 0; j < 4; ++j)
            #pragma unroll
            for (int x = 0; x < 4; ++x) acc[i][j][x] = 0.f;

    int l7 = lane & 7;
    int ra_base = wm * 64 + l7 + ((lane >> 3) & 1) * 8;  // A rows
    int ka_base = (lane >> 4) * 16;                      // A 16B sub-chunk of 32B k-step
    int rb_base = wn * 32 + l7 + (lane >> 4) * 8;        // B n-rows
    int kb_base = ((lane >> 3) & 1) * 16;                // B 16B sub-chunk

    #pragma unroll
    for (int kk = 0; kk < 8; ++kk) {                     // k-step = 32 fp8 = 32 bytes
        uint32_t af[4][4];
        #pragma unroll
        for (int i = 0; i < 4; ++i) {
            int r = ra_base + i * 16;
            uint32_t off = (uint32_t)(r * 256 + kk * 32 + ka_base);
            ldsm_x4(sA + (off ^ ((uint32_t)(r & 7) << 4)), af[i]);
        }
        uint32_t bf[2][4];
        #pragma unroll
        for (int j2 = 0; j2 < 2; ++j2) {
            int r = rb_base + j2 * 16;
            uint32_t off = (uint32_t)(r * 256 + kk * 32 + kb_base);
            ldsm_x4(sB + (off ^ ((uint32_t)(r & 7) << 4)), bf[j2]);
        }
        #pragma unroll
        for (int i = 0; i < 4; ++i)
            #pragma unroll
            for (int j = 0; j < 4; ++j)
                mma16832_e4m3(acc[i][j], af[i], &bf[j >> 1][(j & 1) * 2]);
    }
    __syncthreads();   // smem tiles no longer needed; reuse for reductions

    float* rAcc = (float*)smem;        // 128 row partials (tm rows)
    float* cAcc = rAcc + 128;          // 128 col partials (tn rows, via symmetry)
    ((float*)smem)[tid] = 0.f;
    __syncthreads();

    float rs[4][2], cs[4][2];
    #pragma unroll
    for (int i = 0; i < 4; ++i) { rs[i][0] = 0.f; rs[i][1] = 0.f; }
    #pragma unroll
    for (int j = 0; j < 4; ++j) { cs[j][0] = 0.f; cs[j][1] = 0.f; }

    #pragma unroll
    for (int i = 0; i < 4; ++i) {
        int R0 = wm * 64 + i * 16 + g, R1 = R0 + 8;
        #pragma unroll
        for (int j = 0; j < 4; ++j) {
            int C0 = wn * 32 + j * 8 + 2 * q, C1 = C0 + 1;
            float e00 = __expf(2.0f * acc[i][j][0]);  // logits = sim / 0.5
            float e01 = __expf(2.0f * acc[i][j][1]);
            float e10 = __expf(2.0f * acc[i][j][2]);
            float e11 = __expf(2.0f * acc[i][j][3]);
            if (diag) {                               // mask self-diagonal
                if (R0 == C0) e00 = 0.f;
                if (R0 == C1) e01 = 0.f;
                if (R1 == C0) e10 = 0.f;
                if (R1 == C1) e11 = 0.f;
            }
            rs[i][0] += e00 + e01;  rs[i][1] += e10 + e11;
            cs[j][0] += e00 + e10;  cs[j][1] += e01 + e11;
        }
    }
    // row partials: lanes sharing g share rows -> reduce over q
    #pragma unroll
    for (int i = 0; i < 4; ++i)
        #pragma unroll
        for (int h = 0; h < 2; ++h) {
            float v = rs[i][h];
            v += __shfl_xor_sync(0xFFFFFFFFu, v, 1);
            v += __shfl_xor_sync(0xFFFFFFFFu, v, 2);
            if (q == 0) atomicAdd(&rAcc[wm * 64 + i * 16 + g + h * 8], v);
        }
    // col partials: lanes sharing q share cols -> reduce over g (off-diagonal tiles)
    if (!diag) {
        #pragma unroll
        for (int j = 0; j < 4; ++j)
            #pragma unroll
            for (int h = 0; h < 2; ++h) {
                float v = cs[j][h];
                v += __shfl_xor_sync(0xFFFFFFFFu, v, 4);
                v += __shfl_xor_sync(0xFFFFFFFFu, v, 8);
                v += __shfl_xor_sync(0xFFFFFFFFu, v, 16);
                if (g == 0) atomicAdd(&cAcc[wn * 32 + j * 8 + 2 * q + h], v);
            }
    }
    __syncthreads();
    if (tid < 128) {
        atomicAdd(&g_rowsum[tm * 128 + tid], rAcc[tid]);
        if (!diag) atomicAdd(&g_rowsum[tn * 128 + tid], cAcc[tid]);
    }
}

// ---------------- kernel 3: per-row log + positive subtraction -> 64 partials --------
__global__ void k_rowred() {
    __shared__ float sh[4];
    int r = blockIdx.x * 128 + threadIdx.x;  // 64 * 128 = 8192 rows
    float v = logf(g_rowsum[r]) - 2.0f * g_pos[r & (NPAIRS - 1)];
    #pragma unroll
    for (int o = 16; o; o >>= 1) v += __shfl_xor_sync(0xFFFFFFFFu, v, o);
    if ((threadIdx.x & 31) == 0) sh[threadIdx.x >> 5] = v;
    __syncthreads();
    if (threadIdx.x == 0) g_partials[blockIdx.x] = sh[0] + sh[1] + sh[2] + sh[3];
}

// ---------------- kernel 4: final reduce ----------------
__global__ void k_final(float* __restrict__ out) {
    int l = threadIdx.x;
    float v = g_partials[l] + g_partials[l + 32];
    #pragma unroll
    for (int o = 16; o; o >>= 1) v += __shfl_xor_sync(0xFFFFFFFFu, v, o);
    if (l == 0) out[0] = v / (float)TWO_N;
}

// ---------------- launch ----------------
extern "C" void kernel_launch(void* const* d_in, const int* in_sizes, int n_in,
                              void* d_out, int out_size) {
    const float* zis = (const float*)d_in[0];
    const float* zjs = (const float*)d_in[1];
    float* out = (float*)d_out;

    cudaFuncSetAttribute(k_gemm, cudaFuncAttributeMaxDynamicSharedMemorySize, SMEM_TOTAL);

    k_norm<<<512, 256>>>(zis, zjs);
    k_gemm<<<NTRI, 256, SMEM_TOTAL>>>();
    k_rowred<<<64, 128>>>();
    k_final<<<1, 32>>>(out);
}